// round 6
// baseline (speedup 1.0000x reference)
#include <cuda_runtime.h>
#include <cstdint>
#include <cstddef>

#define Bn  64
#define Tn  512
#define DIn 512
#define Hn  1024
#define G4n 4096

typedef unsigned long long ull;

// Scratch for the precomputed input projection: (B, T, 4H) fp32 = 512 MB.
__device__ float g_xproj[(size_t)Bn * Tn * G4n];

#define NCTA    128
// Per-CTA monotonic step flags for the distributed grid barrier.
__device__ ull g_flags[NCTA];

// ---------------- packed f32x2 helpers (exact fp32, 2x FFMA throughput) ----
__device__ __forceinline__ ull pack2(float lo, float hi) {
    ull r;
    asm("mov.b64 %0, {%1, %2};" : "=l"(r) : "f"(lo), "f"(hi));
    return r;
}
__device__ __forceinline__ void fma2(ull& d, ull a, ull b) {
    asm("fma.rn.f32x2 %0, %1, %2, %0;" : "+l"(d) : "l"(a), "l"(b));
}
__device__ __forceinline__ ull add2(ull a, ull b) {
    ull r;
    asm("add.rn.f32x2 %0, %1, %2;" : "=l"(r) : "l"(a), "l"(b));
    return r;
}
__device__ __forceinline__ float2 unpack2(ull v) {
    float lo, hi;
    asm("mov.b64 {%0, %1}, %2;" : "=f"(lo), "=f"(hi) : "l"(v));
    return make_float2(lo, hi);
}
__device__ __forceinline__ float hadd2(ull v) {
    float2 p = unpack2(v);
    return p.x + p.y;
}

__device__ __forceinline__ float sigf(float x) {
    return 1.0f / (1.0f + __expf(-x));
}

// ============================================================================
// Kernel 1: x_proj = inputs @ W_ih^T + (b_ih + b_hh)
//   128x128x32 tile, 256 threads, 8x8/thread (f32x2 col pairs). fma ~69%.
// ============================================================================
#define XK 32
__global__ __launch_bounds__(256, 2) void xproj_kernel(
    const float* __restrict__ A,      // (M, K)
    const float* __restrict__ Wih,    // (N, K)
    const float* __restrict__ bih,
    const float* __restrict__ bhh)
{
    __shared__ float sA[XK][132];
    __shared__ float sB[XK][132];

    const int tid = threadIdx.x;
    const int tx  = tid & 15;
    const int ty  = tid >> 4;
    const int n0  = blockIdx.x * 128;
    const int m0  = blockIdx.y * 128;

    ull acc[8][4];
#pragma unroll
    for (int r = 0; r < 8; ++r)
#pragma unroll
        for (int c = 0; c < 4; ++c) acc[r][c] = 0ULL;

    for (int k0 = 0; k0 < DIn; k0 += XK) {
#pragma unroll
        for (int it = 0; it < 4; ++it) {
            int i = tid + it * 256;
            int q = i & 7;
            int r = i >> 3;
            float4 va = *(const float4*)&A[(size_t)(m0 + r) * DIn + k0 + 4 * q];
            sA[4 * q + 0][r] = va.x; sA[4 * q + 1][r] = va.y;
            sA[4 * q + 2][r] = va.z; sA[4 * q + 3][r] = va.w;
            float4 vb = *(const float4*)&Wih[(size_t)(n0 + r) * DIn + k0 + 4 * q];
            sB[4 * q + 0][r] = vb.x; sB[4 * q + 1][r] = vb.y;
            sB[4 * q + 2][r] = vb.z; sB[4 * q + 3][r] = vb.w;
        }
        __syncthreads();

#pragma unroll
        for (int kk = 0; kk < XK; ++kk) {
            float4 a0 = *(const float4*)&sA[kk][8 * ty];
            float4 a1 = *(const float4*)&sA[kk][8 * ty + 4];
            ull b0 = *(const ull*)&sB[kk][2 * tx];
            ull b1 = *(const ull*)&sB[kk][2 * tx + 32];
            ull b2 = *(const ull*)&sB[kk][2 * tx + 64];
            ull b3 = *(const ull*)&sB[kk][2 * tx + 96];
            ull A0 = pack2(a0.x, a0.x), A1 = pack2(a0.y, a0.y);
            ull A2 = pack2(a0.z, a0.z), A3 = pack2(a0.w, a0.w);
            ull A4 = pack2(a1.x, a1.x), A5 = pack2(a1.y, a1.y);
            ull A6 = pack2(a1.z, a1.z), A7 = pack2(a1.w, a1.w);
            fma2(acc[0][0], A0, b0); fma2(acc[0][1], A0, b1);
            fma2(acc[0][2], A0, b2); fma2(acc[0][3], A0, b3);
            fma2(acc[1][0], A1, b0); fma2(acc[1][1], A1, b1);
            fma2(acc[1][2], A1, b2); fma2(acc[1][3], A1, b3);
            fma2(acc[2][0], A2, b0); fma2(acc[2][1], A2, b1);
            fma2(acc[2][2], A2, b2); fma2(acc[2][3], A2, b3);
            fma2(acc[3][0], A3, b0); fma2(acc[3][1], A3, b1);
            fma2(acc[3][2], A3, b2); fma2(acc[3][3], A3, b3);
            fma2(acc[4][0], A4, b0); fma2(acc[4][1], A4, b1);
            fma2(acc[4][2], A4, b2); fma2(acc[4][3], A4, b3);
            fma2(acc[5][0], A5, b0); fma2(acc[5][1], A5, b1);
            fma2(acc[5][2], A5, b2); fma2(acc[5][3], A5, b3);
            fma2(acc[6][0], A6, b0); fma2(acc[6][1], A6, b1);
            fma2(acc[6][2], A6, b2); fma2(acc[6][3], A6, b3);
            fma2(acc[7][0], A7, b0); fma2(acc[7][1], A7, b1);
            fma2(acc[7][2], A7, b2); fma2(acc[7][3], A7, b3);
        }
        __syncthreads();
    }

    ull bp[4];
#pragma unroll
    for (int cp = 0; cp < 4; ++cp) {
        int c0 = n0 + 32 * cp + 2 * tx;
        bp[cp] = pack2(bih[c0] + bhh[c0], bih[c0 + 1] + bhh[c0 + 1]);
    }
#pragma unroll
    for (int r = 0; r < 8; ++r) {
        int row = m0 + 8 * ty + r;
#pragma unroll
        for (int cp = 0; cp < 4; ++cp) {
            ull d = add2(acc[r][cp], bp[cp]);
            *(ull*)&g_xproj[(size_t)row * G4n + n0 + 32 * cp + 2 * tx] = d;
        }
    }
}

// ============================================================================
// Persistent recurrence kernel (128 CTAs x 256 thr, W_hh pinned in SMEM).
//   R5: k-paired FFMA2 inner loop (both operands LDS.64, no pack2 in loop,
//   57% FFMA2 issue density), thread cols = one column per gate so the LSTM
//   combine is fully thread-local (sg staging buffer deleted).
//   Accumulator lanes hold (even k, odd k) partial sums; horizontal add once.
// ============================================================================
#define NTHR    256
#define WP      66           // W pair-row pad: 32 cols x 2 floats + 2
#define SH_PAD  132          // h row pad (16B-aligned rows for cp.async)
#define CHUNK   128          // k per chunk
#define NPAIR   (CHUNK / 2)  // 64 k-pairs per chunk
#define NCHUNK  (Hn / CHUNK)

#define SW_FLOATS ((Hn / 2) * WP)          // 512 pair-rows * 66 = 33792
#define SH_FLOATS (2 * Bn * SH_PAD)        // 16896
#define SMEM_BYTES ((SW_FLOATS + SH_FLOATS) * 4 + 16)   // ~203 KB

__device__ __forceinline__ void cp_async16(uint32_t dst, const void* src) {
    asm volatile("cp.async.cg.shared.global [%0], [%1], 16;\n" :: "r"(dst), "l"(src));
}
__device__ __forceinline__ void cp_commit() {
    asm volatile("cp.async.commit_group;\n");
}
template <int N>
__device__ __forceinline__ void cp_wait() {
    asm volatile("cp.async.wait_group %0;\n" :: "n"(N));
}

__device__ __forceinline__ void load_h_chunk(uint32_t sh_addr, const float* __restrict__ hs,
                                             int tprev, int kt, int buf, int tid) {
    const int k0 = kt * CHUNK;
#pragma unroll
    for (int it = 0; it < 8; ++it) {
        int i  = tid + it * NTHR;
        int kc = i & 31;
        int r  = i >> 5;
        const float* src = &hs[((size_t)r * Tn + tprev) * Hn + k0 + 4 * kc];
        uint32_t dst = sh_addr + (uint32_t)(((buf * Bn + r) * SH_PAD + 4 * kc) * 4);
        cp_async16(dst, src);
    }
}

__global__ __launch_bounds__(NTHR, 1) void lstm_persistent(
    const float* __restrict__ Whh,   // (4H, H)
    float* __restrict__ hs,          // (B, T, H)
    float* __restrict__ cs)          // (B, T, H)
{
    extern __shared__ float smem[];
    float* sw = smem;                          // [Hn/2][WP]  W k-pair-interleaved
    float* sh = sw + SW_FLOATS;                // [2][Bn][SH_PAD] h double buffer
    ull* s_base = (ull*)(sh + SH_FLOATS);

    const int tid = threadIdx.x;
    const int g   = tid & 7;       // H-column within the CTA's 8-col slice
    const int rg  = tid >> 3;      // 2-row group, 0..31
    const int j0  = blockIdx.x * 8;

    // ---- load W slice into SMEM as k-pairs, once ----
    // sw[kp*WP + 2*c + {0,1}] = W[gate*H + j0+jj][2*kp + {0,1}], c = gate*8+jj
#pragma unroll 4
    for (int it = 0; it < 32; ++it) {
        int i  = tid + it * NTHR;
        int c  = i & 31;                 // c = gate*8 + jj
        int kq = i >> 5;                 // float4 index along k, 0..255
        int gate = c >> 3, jj = c & 7;
        const float4 v = *(const float4*)&Whh[(size_t)(gate * Hn + j0 + jj) * Hn + 4 * kq];
        sw[(2 * kq + 0) * WP + 2 * c + 0] = v.x;
        sw[(2 * kq + 0) * WP + 2 * c + 1] = v.y;
        sw[(2 * kq + 1) * WP + 2 * c + 0] = v.z;
        sw[(2 * kq + 1) * WP + 2 * c + 1] = v.w;
    }

    // ---- recover barrier base (monotonic flags; equal across CTAs at start)
    if (tid == 0) *s_base = g_flags[blockIdx.x];
    __syncthreads();
    const ull base = *s_base;

    const uint32_t sh_addr = (uint32_t)__cvta_generic_to_shared(sh);

    // c state in registers: thread owns cells (2rg, j0+g) and (2rg+1, j0+g).
    float creg[2] = {0.0f, 0.0f};
    const int b0r = 2 * rg;
    const int j   = j0 + g;

    for (int t = 0; t < Tn; ++t) {
        // ---- kick off first h chunk ASAP ----
        if (t > 0) {
            load_h_chunk(sh_addr, hs, t - 1, 0, 0, tid);
            cp_commit();
        }

        // ---- prefetch x_proj for this thread's 2 cells (used in epilogue) --
        float xpv[2][4];
#pragma unroll
        for (int it = 0; it < 2; ++it) {
            const float* xp = &g_xproj[((size_t)(b0r + it) * Tn + t) * G4n + j];
            xpv[it][0] = xp[0];
            xpv[it][1] = xp[Hn];
            xpv[it][2] = xp[2 * Hn];
            xpv[it][3] = xp[3 * Hn];
        }

        // acc[row][gate], lanes = (even-k, odd-k) partial sums
        ull acc[2][4];
#pragma unroll
        for (int r = 0; r < 2; ++r)
#pragma unroll
            for (int q = 0; q < 4; ++q) acc[r][q] = 0ULL;

        if (t > 0) {
#pragma unroll 1
            for (int kt = 0; kt < NCHUNK; ++kt) {
                if (kt + 1 < NCHUNK) {
                    load_h_chunk(sh_addr, hs, t - 1, kt + 1, (kt + 1) & 1, tid);
                    cp_commit();
                    cp_wait<1>();
                } else {
                    cp_wait<0>();
                }
                __syncthreads();

                const float* hb = sh + ((kt & 1) * Bn + b0r) * SH_PAD;
                const float* wb = sw + (size_t)(kt * NPAIR) * WP + 2 * g;
#pragma unroll 16
                for (int kp = 0; kp < NPAIR; ++kp) {
                    ull hA = *(const ull*)&hb[2 * kp];             // h[row0][2kp, 2kp+1]
                    ull hB = *(const ull*)&hb[SH_PAD + 2 * kp];    // h[row1][...]
                    ull w0 = *(const ull*)&wb[kp * WP];            // gate i
                    ull w1 = *(const ull*)&wb[kp * WP + 16];       // gate f
                    ull w2 = *(const ull*)&wb[kp * WP + 32];       // gate g
                    ull w3 = *(const ull*)&wb[kp * WP + 48];       // gate o
                    fma2(acc[0][0], hA, w0); fma2(acc[0][1], hA, w1);
                    fma2(acc[0][2], hA, w2); fma2(acc[0][3], hA, w3);
                    fma2(acc[1][0], hB, w0); fma2(acc[1][1], hB, w1);
                    fma2(acc[1][2], hB, w2); fma2(acc[1][3], hB, w3);
                }
                __syncthreads();
            }
        }

        // ---- thread-local LSTM gate combine: 2 cells, no SMEM staging ----
#pragma unroll
        for (int it = 0; it < 2; ++it) {
            float gi = hadd2(acc[it][0]) + xpv[it][0];
            float gf = hadd2(acc[it][1]) + xpv[it][1];
            float gg = hadd2(acc[it][2]) + xpv[it][2];
            float go = hadd2(acc[it][3]) + xpv[it][3];
            float iv = sigf(gi);
            float fv = sigf(gf);
            float gv = tanhf(gg);
            float ov = sigf(go);
            float cn = fv * creg[it] + iv * gv;
            float hn = ov * tanhf(cn);
            creg[it] = cn;
            size_t o = ((size_t)(b0r + it) * Tn + t) * Hn + j;
            hs[o] = hn;
            cs[o] = cn;
        }

        // ---- distributed grid barrier between steps ----
        if (t < Tn - 1) {
            __syncthreads();                       // all hs/cs stores issued
            if (tid == 0) {
                asm volatile("st.release.gpu.global.u64 [%0], %1;"
                             :: "l"(&g_flags[blockIdx.x]),
                                "l"(base + (ull)(t + 1)) : "memory");
            }
            if (tid < NCTA) {
                const ull target = base + (ull)(t + 1);
                ull v;
                do {
                    asm volatile("ld.acquire.gpu.global.u64 %0, [%1];"
                                 : "=l"(v) : "l"(&g_flags[tid]) : "memory");
                    if (v < target) __nanosleep(20);
                } while (v < target);
            }
            __syncthreads();
        }
    }
}

// ============================================================================
// Kernel 3: gather h_last / c_last via length
// ============================================================================
__global__ void gather_kernel(const float* __restrict__ hs,
                              const float* __restrict__ cs,
                              const int* __restrict__ length,
                              float* __restrict__ h_last,
                              float* __restrict__ c_last)
{
    int b = blockIdx.x;
    int j = threadIdx.x;
    int t = length[b] - 1;
    size_t src = ((size_t)b * Tn + t) * Hn + j;
    size_t dst = (size_t)b * Hn + j;
    h_last[dst] = hs[src];
    c_last[dst] = cs[src];
}

// ============================================================================
extern "C" void kernel_launch(void* const* d_in, const int* in_sizes, int n_in,
                              void* d_out, int out_size)
{
    (void)in_sizes; (void)n_in; (void)out_size;
    const float* inputs = (const float*)d_in[0];   // (B, T, DI)
    const float* W_ih   = (const float*)d_in[1];   // (4H, DI)
    const float* W_hh   = (const float*)d_in[2];   // (4H, H)
    const float* b_ih   = (const float*)d_in[3];   // (4H,)
    const float* b_hh   = (const float*)d_in[4];   // (4H,)
    const int*   length = (const int*)d_in[5];     // (B,)

    float* out    = (float*)d_out;
    float* hs     = out;                                   // (B, T, H)
    float* cs     = hs + (size_t)Bn * Tn * Hn;             // (B, T, H)
    float* h_last = cs + (size_t)Bn * Tn * Hn;             // (B, H)
    float* c_last = h_last + (size_t)Bn * Hn;              // (B, H)

    // 1) x_proj = inputs @ W_ih^T + (b_ih + b_hh)
    dim3 g1(G4n / 128, (Bn * Tn) / 128);
    xproj_kernel<<<g1, 256>>>(inputs, W_ih, b_ih, b_hh);

    // 2) persistent recurrence (single launch, distributed flag barrier)
    cudaFuncSetAttribute(lstm_persistent,
                         cudaFuncAttributeMaxDynamicSharedMemorySize, SMEM_BYTES);
    lstm_persistent<<<NCTA, NTHR, SMEM_BYTES>>>(W_hh, hs, cs);

    // 3) gather last valid states
    gather_kernel<<<Bn, Hn>>>(hs, cs, length, h_last, c_last);
}

// round 11
// speedup vs baseline: 1.0321x; 1.0321x over previous
#include <cuda_runtime.h>
#include <cstdint>
#include <cstddef>

#define Bn  64
#define Tn  512
#define DIn 512
#define Hn  1024
#define G4n 4096

typedef unsigned long long ull;

// Scratch for the precomputed input projection: (B, T, 4H) fp32 = 512 MB.
__device__ float g_xproj[(size_t)Bn * Tn * G4n];

#define NCTA    128
// Per-CTA monotonic step flags: flag[b] = base + (completed steps).
__device__ ull g_flags[NCTA];

// ---------------- packed f32x2 helpers (exact fp32, 2x FFMA throughput) ----
__device__ __forceinline__ ull pack2(float lo, float hi) {
    ull r;
    asm("mov.b64 %0, {%1, %2};" : "=l"(r) : "f"(lo), "f"(hi));
    return r;
}
__device__ __forceinline__ void fma2(ull& d, ull a, ull b) {
    asm("fma.rn.f32x2 %0, %1, %2, %0;" : "+l"(d) : "l"(a), "l"(b));
}
__device__ __forceinline__ ull add2(ull a, ull b) {
    ull r;
    asm("add.rn.f32x2 %0, %1, %2;" : "=l"(r) : "l"(a), "l"(b));
    return r;
}
__device__ __forceinline__ float2 unpack2(ull v) {
    float lo, hi;
    asm("mov.b64 {%0, %1}, %2;" : "=f"(lo), "=f"(hi) : "l"(v));
    return make_float2(lo, hi);
}
__device__ __forceinline__ float hadd2(ull v) {
    float2 p = unpack2(v);
    return p.x + p.y;
}

__device__ __forceinline__ float sigf(float x) {
    return 1.0f / (1.0f + __expf(-x));
}

// ============================================================================
// Kernel 1: x_proj = inputs @ W_ih^T + (b_ih + b_hh)
//   128x128x32 tile, 256 threads, 8x8/thread (f32x2 col pairs). fma ~69%.
// ============================================================================
#define XK 32
__global__ __launch_bounds__(256, 2) void xproj_kernel(
    const float* __restrict__ A,      // (M, K)
    const float* __restrict__ Wih,    // (N, K)
    const float* __restrict__ bih,
    const float* __restrict__ bhh)
{
    __shared__ float sA[XK][132];
    __shared__ float sB[XK][132];

    const int tid = threadIdx.x;
    const int tx  = tid & 15;
    const int ty  = tid >> 4;
    const int n0  = blockIdx.x * 128;
    const int m0  = blockIdx.y * 128;

    ull acc[8][4];
#pragma unroll
    for (int r = 0; r < 8; ++r)
#pragma unroll
        for (int c = 0; c < 4; ++c) acc[r][c] = 0ULL;

    for (int k0 = 0; k0 < DIn; k0 += XK) {
#pragma unroll
        for (int it = 0; it < 4; ++it) {
            int i = tid + it * 256;
            int q = i & 7;
            int r = i >> 3;
            float4 va = *(const float4*)&A[(size_t)(m0 + r) * DIn + k0 + 4 * q];
            sA[4 * q + 0][r] = va.x; sA[4 * q + 1][r] = va.y;
            sA[4 * q + 2][r] = va.z; sA[4 * q + 3][r] = va.w;
            float4 vb = *(const float4*)&Wih[(size_t)(n0 + r) * DIn + k0 + 4 * q];
            sB[4 * q + 0][r] = vb.x; sB[4 * q + 1][r] = vb.y;
            sB[4 * q + 2][r] = vb.z; sB[4 * q + 3][r] = vb.w;
        }
        __syncthreads();

#pragma unroll
        for (int kk = 0; kk < XK; ++kk) {
            float4 a0 = *(const float4*)&sA[kk][8 * ty];
            float4 a1 = *(const float4*)&sA[kk][8 * ty + 4];
            ull b0 = *(const ull*)&sB[kk][2 * tx];
            ull b1 = *(const ull*)&sB[kk][2 * tx + 32];
            ull b2 = *(const ull*)&sB[kk][2 * tx + 64];
            ull b3 = *(const ull*)&sB[kk][2 * tx + 96];
            ull A0 = pack2(a0.x, a0.x), A1 = pack2(a0.y, a0.y);
            ull A2 = pack2(a0.z, a0.z), A3 = pack2(a0.w, a0.w);
            ull A4 = pack2(a1.x, a1.x), A5 = pack2(a1.y, a1.y);
            ull A6 = pack2(a1.z, a1.z), A7 = pack2(a1.w, a1.w);
            fma2(acc[0][0], A0, b0); fma2(acc[0][1], A0, b1);
            fma2(acc[0][2], A0, b2); fma2(acc[0][3], A0, b3);
            fma2(acc[1][0], A1, b0); fma2(acc[1][1], A1, b1);
            fma2(acc[1][2], A1, b2); fma2(acc[1][3], A1, b3);
            fma2(acc[2][0], A2, b0); fma2(acc[2][1], A2, b1);
            fma2(acc[2][2], A2, b2); fma2(acc[2][3], A2, b3);
            fma2(acc[3][0], A3, b0); fma2(acc[3][1], A3, b1);
            fma2(acc[3][2], A3, b2); fma2(acc[3][3], A3, b3);
            fma2(acc[4][0], A4, b0); fma2(acc[4][1], A4, b1);
            fma2(acc[4][2], A4, b2); fma2(acc[4][3], A4, b3);
            fma2(acc[5][0], A5, b0); fma2(acc[5][1], A5, b1);
            fma2(acc[5][2], A5, b2); fma2(acc[5][3], A5, b3);
            fma2(acc[6][0], A6, b0); fma2(acc[6][1], A6, b1);
            fma2(acc[6][2], A6, b2); fma2(acc[6][3], A6, b3);
            fma2(acc[7][0], A7, b0); fma2(acc[7][1], A7, b1);
            fma2(acc[7][2], A7, b2); fma2(acc[7][3], A7, b3);
        }
        __syncthreads();
    }

    ull bp[4];
#pragma unroll
    for (int cp = 0; cp < 4; ++cp) {
        int c0 = n0 + 32 * cp + 2 * tx;
        bp[cp] = pack2(bih[c0] + bhh[c0], bih[c0 + 1] + bhh[c0 + 1]);
    }
#pragma unroll
    for (int r = 0; r < 8; ++r) {
        int row = m0 + 8 * ty + r;
#pragma unroll
        for (int cp = 0; cp < 4; ++cp) {
            ull d = add2(acc[r][cp], bp[cp]);
            *(ull*)&g_xproj[(size_t)row * G4n + n0 + 32 * cp + 2 * tx] = d;
        }
    }
}

// ============================================================================
// Persistent recurrence kernel (128 CTAs x 256 thr, W_hh pinned in SMEM).
//   R7: (a) W re-layout so each thread's 4 gate k-pairs are 2 LDS.128
//   (4 wavefronts per kp, was 6 — kernel is SMEM-crossbar bound);
//   (b) per-chunk producer flags replace the global barrier: chunk ka needs
//   only CTAs [16ka,16ka+16); hs/cs are time-indexed so no WAR hazards and
//   CTAs pipeline across steps. Chunk order rotated per CTA (own group first).
// ============================================================================
#define NTHR    256
#define WP      68           // W row: 64 floats (2 x 32 gate-pair blocks) + 4 pad
#define SH_PAD  132          // h row pad (16B-aligned rows for cp.async)
#define CHUNK   128          // k per chunk
#define NPAIR   (CHUNK / 2)  // 64 k-pairs per chunk
#define NCHUNK  (Hn / CHUNK) // 8

#define SW_FLOATS ((Hn / 2) * WP)          // 512 * 68 = 34816
#define SH_FLOATS (2 * Bn * SH_PAD)        // 16896
#define SMEM_BYTES ((SW_FLOATS + SH_FLOATS) * 4 + 16)   // ~207 KB

__device__ __forceinline__ void cp_async16(uint32_t dst, const void* src) {
    asm volatile("cp.async.cg.shared.global [%0], [%1], 16;\n" :: "r"(dst), "l"(src));
}
__device__ __forceinline__ void cp_commit() {
    asm volatile("cp.async.commit_group;\n");
}
template <int N>
__device__ __forceinline__ void cp_wait() {
    asm volatile("cp.async.wait_group %0;\n" :: "n"(N));
}

__device__ __forceinline__ void load_h_chunk(uint32_t sh_addr, const float* __restrict__ hs,
                                             int tprev, int ka, int buf, int tid) {
    const int k0 = ka * CHUNK;
#pragma unroll
    for (int it = 0; it < 8; ++it) {
        int i  = tid + it * NTHR;
        int kc = i & 31;
        int r  = i >> 5;
        const float* src = &hs[((size_t)r * Tn + tprev) * Hn + k0 + 4 * kc];
        uint32_t dst = sh_addr + (uint32_t)(((buf * Bn + r) * SH_PAD + 4 * kc) * 4);
        cp_async16(dst, src);
    }
}

// Wait until producers of chunk ka have published step `t-1` data (flag >= target).
__device__ __forceinline__ void poll_group(int ka, ull target) {
    if (threadIdx.x < 16) {
        const ull* f = &g_flags[ka * 16 + threadIdx.x];
        ull v;
        do {
            asm volatile("ld.acquire.gpu.global.u64 %0, [%1];"
                         : "=l"(v) : "l"(f) : "memory");
            if (v < target) __nanosleep(20);
        } while (v < target);
    }
}

__global__ __launch_bounds__(NTHR, 1) void lstm_persistent(
    const float* __restrict__ Whh,   // (4H, H)
    float* __restrict__ hs,          // (B, T, H)
    float* __restrict__ cs)          // (B, T, H)
{
    extern __shared__ float smem[];
    float* sw = smem;                          // [Hn/2][WP]  W gate-pair blocks
    float* sh = sw + SW_FLOATS;                // [2][Bn][SH_PAD] h double buffer
    ull* s_base = (ull*)(sh + SH_FLOATS);

    const int tid = threadIdx.x;
    const int g   = tid & 7;       // H-column within the CTA's 8-col slice
    const int rg  = tid >> 3;      // 2-row group, 0..31
    const int j0  = blockIdx.x * 8;
    const int cstart = (blockIdx.x >> 4) & 7;   // chunk rotation: own group first

    // ---- load W slice into SMEM, gate-pair-blocked, once ----
    // Row kp (64 floats): [0..31] = per-jj {i0,i1,f0,f1}; [32..63] = {g0,g1,o0,o1}.
#pragma unroll 4
    for (int it = 0; it < 32; ++it) {
        int i  = tid + it * NTHR;
        int c  = i & 31;                 // c = gate*8 + jj
        int kq = i >> 5;                 // float4 index along k, 0..255
        int gate = c >> 3, jj = c & 7;
        const float4 v = *(const float4*)&Whh[(size_t)(gate * Hn + j0 + jj) * Hn + 4 * kq];
        int blk = (gate < 2) ? 0 : 32;
        int off = blk + jj * 4 + (gate & 1) * 2;
        sw[(2 * kq + 0) * WP + off + 0] = v.x;
        sw[(2 * kq + 0) * WP + off + 1] = v.y;
        sw[(2 * kq + 1) * WP + off + 0] = v.z;
        sw[(2 * kq + 1) * WP + off + 1] = v.w;
    }

    // ---- flag base (all flags equal at launch start; monotonic across replays)
    if (tid == 0) *s_base = g_flags[blockIdx.x];
    __syncthreads();
    const ull base = *s_base;

    const uint32_t sh_addr = (uint32_t)__cvta_generic_to_shared(sh);

    // c state in registers: thread owns cells (2rg, j0+g) and (2rg+1, j0+g).
    float creg[2] = {0.0f, 0.0f};
    const int b0r = 2 * rg;
    const int j   = j0 + g;

    for (int t = 0; t < Tn; ++t) {
        const ull target = base + (ull)t;   // producers must have completed step t-1

        // ---- prefetch x_proj for this thread's 2 cells (overlaps polls) ----
        float xpv[2][4];
#pragma unroll
        for (int it = 0; it < 2; ++it) {
            const float* xp = &g_xproj[((size_t)(b0r + it) * Tn + t) * G4n + j];
            xpv[it][0] = xp[0];
            xpv[it][1] = xp[Hn];
            xpv[it][2] = xp[2 * Hn];
            xpv[it][3] = xp[3 * Hn];
        }

        // acc[row][gate], lanes = (even-k, odd-k) partial sums
        ull acc[2][4];
#pragma unroll
        for (int r = 0; r < 2; ++r)
#pragma unroll
            for (int q = 0; q < 4; ++q) acc[r][q] = 0ULL;

        if (t > 0) {
            // chunk 0: wait on its 16 producers, then start the async load
            {
                int ka0 = cstart;
                poll_group(ka0, target);
                __syncthreads();
                load_h_chunk(sh_addr, hs, t - 1, ka0, 0, tid);
                cp_commit();
            }
#pragma unroll 1
            for (int kt = 0; kt < NCHUNK; ++kt) {
                const int ka = (cstart + kt) & (NCHUNK - 1);
                if (kt + 1 < NCHUNK) {
                    const int kn = (cstart + kt + 1) & (NCHUNK - 1);
                    poll_group(kn, target);
                    __syncthreads();       // polls done; prev compute of this buf done
                    load_h_chunk(sh_addr, hs, t - 1, kn, (kt + 1) & 1, tid);
                    cp_commit();
                    cp_wait<1>();
                } else {
                    cp_wait<0>();
                }
                __syncthreads();           // chunk kt data complete (all threads)

                const float* hb = sh + ((kt & 1) * Bn + b0r) * SH_PAD;
                const float* wb = sw + (size_t)(ka * NPAIR) * WP + 4 * g;
#pragma unroll 16
                for (int kp = 0; kp < NPAIR; ++kp) {
                    ull hA = *(const ull*)&hb[2 * kp];             // h[row0] k-pair
                    ull hB = *(const ull*)&hb[SH_PAD + 2 * kp];    // h[row1] k-pair
                    ulonglong2 wif = *(const ulonglong2*)&wb[kp * WP];        // i,f pairs
                    ulonglong2 wgo = *(const ulonglong2*)&wb[kp * WP + 32];   // g,o pairs
                    fma2(acc[0][0], hA, wif.x); fma2(acc[0][1], hA, wif.y);
                    fma2(acc[0][2], hA, wgo.x); fma2(acc[0][3], hA, wgo.y);
                    fma2(acc[1][0], hB, wif.x); fma2(acc[1][1], hB, wif.y);
                    fma2(acc[1][2], hB, wgo.x); fma2(acc[1][3], hB, wgo.y);
                }
            }
        }

        // ---- thread-local LSTM gate combine: 2 cells, no SMEM staging ----
#pragma unroll
        for (int it = 0; it < 2; ++it) {
            float gi = hadd2(acc[it][0]) + xpv[it][0];
            float gf = hadd2(acc[it][1]) + xpv[it][1];
            float gg = hadd2(acc[it][2]) + xpv[it][2];
            float go = hadd2(acc[it][3]) + xpv[it][3];
            float iv = sigf(gi);
            float fv = sigf(gf);
            float gv = tanhf(gg);
            float ov = sigf(go);
            float cn = fv * creg[it] + iv * gv;
            float hn = ov * tanhf(cn);
            creg[it] = cn;
            size_t o = ((size_t)(b0r + it) * Tn + t) * Hn + j;
            hs[o] = hn;
            cs[o] = cn;
        }

        // ---- publish: this CTA's step-t h/c are visible ----
        __threadfence();                   // make this thread's stores GPU-visible
        __syncthreads();                   // ... for all threads in the CTA
        if (tid == 0) {
            asm volatile("st.release.gpu.global.u64 [%0], %1;"
                         :: "l"(&g_flags[blockIdx.x]), "l"(base + (ull)(t + 1))
                         : "memory");
        }
        // no global barrier: next step's per-chunk polls gate progress
    }
}

// ============================================================================
// Kernel 3: gather h_last / c_last via length
// ============================================================================
__global__ void gather_kernel(const float* __restrict__ hs,
                              const float* __restrict__ cs,
                              const int* __restrict__ length,
                              float* __restrict__ h_last,
                              float* __restrict__ c_last)
{
    int b = blockIdx.x;
    int j = threadIdx.x;
    int t = length[b] - 1;
    size_t src = ((size_t)b * Tn + t) * Hn + j;
    size_t dst = (size_t)b * Hn + j;
    h_last[dst] = hs[src];
    c_last[dst] = cs[src];
}

// ============================================================================
extern "C" void kernel_launch(void* const* d_in, const int* in_sizes, int n_in,
                              void* d_out, int out_size)
{
    (void)in_sizes; (void)n_in; (void)out_size;
    const float* inputs = (const float*)d_in[0];   // (B, T, DI)
    const float* W_ih   = (const float*)d_in[1];   // (4H, DI)
    const float* W_hh   = (const float*)d_in[2];   // (4H, H)
    const float* b_ih   = (const float*)d_in[3];   // (4H,)
    const float* b_hh   = (const float*)d_in[4];   // (4H,)
    const int*   length = (const int*)d_in[5];     // (B,)

    float* out    = (float*)d_out;
    float* hs     = out;                                   // (B, T, H)
    float* cs     = hs + (size_t)Bn * Tn * Hn;             // (B, T, H)
    float* h_last = cs + (size_t)Bn * Tn * Hn;             // (B, H)
    float* c_last = h_last + (size_t)Bn * Hn;              // (B, H)

    // 1) x_proj = inputs @ W_ih^T + (b_ih + b_hh)
    dim3 g1(G4n / 128, (Bn * Tn) / 128);
    xproj_kernel<<<g1, 256>>>(inputs, W_ih, b_ih, b_hh);

    // 2) persistent recurrence (single launch, per-chunk producer flags)
    cudaFuncSetAttribute(lstm_persistent,
                         cudaFuncAttributeMaxDynamicSharedMemorySize, SMEM_BYTES);
    lstm_persistent<<<NCTA, NTHR, SMEM_BYTES>>>(W_hh, hs, cs);

    // 3) gather last valid states
    gather_kernel<<<Bn, Hn>>>(hs, cs, length, h_last, c_last);
}